// round 1
// baseline (speedup 1.0000x reference)
#include <cuda_runtime.h>
#include <cuda_fp16.h>
#include <cstdint>

#define T_TOK 8192
#define D_DIM 1024
#define E_EXP 8
#define I_DIM 3072
#define TRX   16384     // T_TOK * 2 expanded rows
#define BM 128
#define BN 64
#define BK 32
#define MAXT 144
#define GRID_TILES 136  // max sum of ceil(count_e/128) = 128 + 8

// ------------------- device scratch (static: no allocation) -------------------
__device__ int    g_topk_idx[TRX];
__device__ float  g_topk_w[TRX];
__device__ int    g_counts[E_EXP];
__device__ int    g_cursor[E_EXP];
__device__ float  g_probs_sum[E_EXP];
__device__ float  g_z2_sum;
__device__ int    g_perm_src[TRX];   // sorted pos -> token index
__device__ int    g_dest[TRX];       // (t,k) -> sorted pos
__device__ int    g_tile_e[MAXT];
__device__ int    g_tile_row[MAXT];
__device__ int    g_tile_nrows[MAXT];
__device__ int    g_ntiles;
__device__ __half g_gated[(size_t)TRX * I_DIM];     // ~100 MB
__device__ float  g_outsorted[(size_t)TRX * D_DIM]; // ~67 MB

__device__ __forceinline__ uint32_t smem_u32(const void* p) {
  return (uint32_t)__cvta_generic_to_shared(p);
}

__device__ __forceinline__ void mma16816(float* c, const uint32_t* a, const uint32_t* b) {
  asm volatile(
    "mma.sync.aligned.m16n8k16.row.col.f32.f16.f16.f32 "
    "{%0,%1,%2,%3}, {%4,%5,%6,%7}, {%8,%9}, {%0,%1,%2,%3};\n"
    : "+f"(c[0]), "+f"(c[1]), "+f"(c[2]), "+f"(c[3])
    : "r"(a[0]), "r"(a[1]), "r"(a[2]), "r"(a[3]), "r"(b[0]), "r"(b[1]));
}

// ------------------------------- small kernels --------------------------------
__global__ void zero_kernel() {
  int t = threadIdx.x;
  if (t < E_EXP) { g_counts[t] = 0; g_cursor[t] = 0; g_probs_sum[t] = 0.f; }
  if (t == 0) { g_z2_sum = 0.f; g_ntiles = 0; }
}

// one warp per token: logits (fp32), softmax, top-2, aux accumulators
__global__ void router_kernel(const float* __restrict__ x, const float* __restrict__ rw) {
  int warp = threadIdx.x >> 5;
  int lane = threadIdx.x & 31;
  int token = blockIdx.x * 8 + warp;
  const float* xr = x + (size_t)token * D_DIM;
  float acc[E_EXP];
#pragma unroll
  for (int e = 0; e < E_EXP; e++) acc[e] = 0.f;
  for (int i = lane; i < D_DIM; i += 32) {
    float xv = xr[i];
    const float4* w4 = reinterpret_cast<const float4*>(rw + (size_t)i * E_EXP);
    float4 wa = w4[0], wb = w4[1];
    acc[0] += xv * wa.x; acc[1] += xv * wa.y; acc[2] += xv * wa.z; acc[3] += xv * wa.w;
    acc[4] += xv * wb.x; acc[5] += xv * wb.y; acc[6] += xv * wb.z; acc[7] += xv * wb.w;
  }
#pragma unroll
  for (int e = 0; e < E_EXP; e++) {
#pragma unroll
    for (int o = 16; o > 0; o >>= 1) acc[e] += __shfl_xor_sync(0xffffffffu, acc[e], o);
  }
  if (lane == 0) {
    float m = acc[0];
#pragma unroll
    for (int e = 1; e < E_EXP; e++) m = fmaxf(m, acc[e]);
    float p[E_EXP]; float se = 0.f;
#pragma unroll
    for (int e = 0; e < E_EXP; e++) { p[e] = expf(acc[e] - m); se += p[e]; }
    float inv = 1.f / se;
#pragma unroll
    for (int e = 0; e < E_EXP; e++) p[e] *= inv;
    float z = m + logf(se);
    atomicAdd(&g_z2_sum, z * z);
#pragma unroll
    for (int e = 0; e < E_EXP; e++) atomicAdd(&g_probs_sum[e], p[e]);
    // top-2 on logits, strict > keeps earliest index on ties (matches jax top_k)
    int i0 = 0;
#pragma unroll
    for (int e = 1; e < E_EXP; e++) if (acc[e] > acc[i0]) i0 = e;
    int i1 = (i0 == 0) ? 1 : 0;
#pragma unroll
    for (int e = 0; e < E_EXP; e++) if (e != i0 && acc[e] > acc[i1]) i1 = e;
    float s = p[i0] + p[i1];
    g_topk_idx[token * 2 + 0] = i0;
    g_topk_idx[token * 2 + 1] = i1;
    g_topk_w[token * 2 + 0] = p[i0] / s;
    g_topk_w[token * 2 + 1] = p[i1] / s;
    atomicAdd(&g_counts[i0], 1);
    atomicAdd(&g_counts[i1], 1);
  }
}

__global__ void scan_kernel() {
  if (threadIdx.x == 0) {
    int off = 0, nt = 0;
    for (int e = 0; e < E_EXP; e++) {
      g_cursor[e] = off;
      int c = g_counts[e];
      for (int r = 0; r < c; r += BM) {
        g_tile_e[nt] = e;
        g_tile_row[nt] = off + r;
        g_tile_nrows[nt] = (c - r < BM) ? (c - r) : BM;
        nt++;
      }
      off += c;
    }
    g_ntiles = nt;
  }
}

__global__ void scatter_kernel() {
  int i = blockIdx.x * 256 + threadIdx.x;
  if (i < TRX) {
    int e = g_topk_idx[i];
    int pos = atomicAdd(&g_cursor[e], 1);
    g_perm_src[pos] = i >> 1;
    g_dest[i] = pos;
  }
}

// ------------------- GEMM1: h1 = Xg*W1, h2 = Xg*W2, gated = silu(h1)*h2 -------------------
__global__ __launch_bounds__(256, 2)
void gemm1_kernel(const float* __restrict__ x, const float* __restrict__ w1,
                  const float* __restrict__ w2) {
  int tile = blockIdx.y;
  if (tile >= g_ntiles) return;
  const int tid = threadIdx.x;
  const int e = g_tile_e[tile];
  const int row0 = g_tile_row[tile];
  const int nrows = g_tile_nrows[tile];
  const int n0 = blockIdx.x * BN;
  const float* __restrict__ W1 = w1 + (size_t)e * D_DIM * I_DIM;
  const float* __restrict__ W2 = w2 + (size_t)e * D_DIM * I_DIM;

  __shared__ __half As[BM][BK + 8];
  __shared__ __half B1s[BK][BN + 8];
  __shared__ __half B2s[BK][BN + 8];
  __shared__ int rowtok[BM];

  if (tid < BM) {
    int r = row0 + tid;
    rowtok[tid] = g_perm_src[r < TRX ? r : TRX - 1];
  }
  __syncthreads();

  float c1[2][4][4];
  float c2[2][4][4];
#pragma unroll
  for (int i = 0; i < 2; i++)
#pragma unroll
    for (int j = 0; j < 4; j++)
#pragma unroll
      for (int q = 0; q < 4; q++) { c1[i][j][q] = 0.f; c2[i][j][q] = 0.f; }

  const int lane = tid & 31;
  const int wid = tid >> 5;
  const int wm = wid >> 1;   // 0..3
  const int wn = wid & 1;    // 0..1

  const int arow = tid & 127;
  const int acs  = (tid >> 7) << 4;   // 0 or 16
  const int brow = tid & 31;
  const int bcs  = (tid >> 5) << 3;   // 0..56

  const float* aptr = x + (size_t)rowtok[arow] * D_DIM + acs;

  for (int k0 = 0; k0 < D_DIM; k0 += BK) {
    // ---- A tile: gather rows, fp32->fp16 ----
    {
      const float* s = aptr + k0;
      float4 f0 = *(const float4*)(s + 0);
      float4 f1 = *(const float4*)(s + 4);
      float4 f2 = *(const float4*)(s + 8);
      float4 f3 = *(const float4*)(s + 12);
      __align__(16) __half t[16];
      t[0]=__float2half(f0.x); t[1]=__float2half(f0.y); t[2]=__float2half(f0.z); t[3]=__float2half(f0.w);
      t[4]=__float2half(f1.x); t[5]=__float2half(f1.y); t[6]=__float2half(f1.z); t[7]=__float2half(f1.w);
      t[8]=__float2half(f2.x); t[9]=__float2half(f2.y); t[10]=__float2half(f2.z); t[11]=__float2half(f2.w);
      t[12]=__float2half(f3.x); t[13]=__float2half(f3.y); t[14]=__float2half(f3.z); t[15]=__float2half(f3.w);
      *(uint4*)&As[arow][acs]     = *(uint4*)t;
      *(uint4*)&As[arow][acs + 8] = *(uint4*)(t + 8);
    }
    // ---- B tiles ----
    {
      size_t g = (size_t)(k0 + brow) * I_DIM + n0 + bcs;
      float4 f0 = *(const float4*)(W1 + g);
      float4 f1 = *(const float4*)(W1 + g + 4);
      __align__(16) __half t[8];
      t[0]=__float2half(f0.x); t[1]=__float2half(f0.y); t[2]=__float2half(f0.z); t[3]=__float2half(f0.w);
      t[4]=__float2half(f1.x); t[5]=__float2half(f1.y); t[6]=__float2half(f1.z); t[7]=__float2half(f1.w);
      *(uint4*)&B1s[brow][bcs] = *(uint4*)t;
      f0 = *(const float4*)(W2 + g);
      f1 = *(const float4*)(W2 + g + 4);
      t[0]=__float2half(f0.x); t[1]=__float2half(f0.y); t[2]=__float2half(f0.z); t[3]=__float2half(f0.w);
      t[4]=__float2half(f1.x); t[5]=__float2half(f1.y); t[6]=__float2half(f1.z); t[7]=__float2half(f1.w);
      *(uint4*)&B2s[brow][bcs] = *(uint4*)t;
    }
    __syncthreads();

#pragma unroll
    for (int kk = 0; kk < BK; kk += 16) {
      uint32_t a[2][4];
#pragma unroll
      for (int mf = 0; mf < 2; mf++) {
        uint32_t ad = smem_u32(&As[wm * 32 + mf * 16 + (lane & 15)][kk + ((lane >> 4) << 3)]);
        asm volatile("ldmatrix.sync.aligned.m8n8.x4.shared.b16 {%0,%1,%2,%3}, [%4];"
          : "=r"(a[mf][0]), "=r"(a[mf][1]), "=r"(a[mf][2]), "=r"(a[mf][3]) : "r"(ad));
      }
#pragma unroll
      for (int nf = 0; nf < 4; nf++) {
        uint32_t b[2];
        uint32_t ad1 = smem_u32(&B1s[kk + (lane & 15)][wn * 32 + nf * 8]);
        asm volatile("ldmatrix.sync.aligned.m8n8.x2.trans.shared.b16 {%0,%1}, [%2];"
          : "=r"(b[0]), "=r"(b[1]) : "r"(ad1));
        mma16816(c1[0][nf], a[0], b);
        mma16816(c1[1][nf], a[1], b);
        uint32_t ad2 = smem_u32(&B2s[kk + (lane & 15)][wn * 32 + nf * 8]);
        asm volatile("ldmatrix.sync.aligned.m8n8.x2.trans.shared.b16 {%0,%1}, [%2];"
          : "=r"(b[0]), "=r"(b[1]) : "r"(ad2));
        mma16816(c2[0][nf], a[0], b);
        mma16816(c2[1][nf], a[1], b);
      }
    }
    __syncthreads();
  }

  // ---- epilogue: gated = silu(h1) * h2 -> fp16 ----
  const int grp = lane >> 2;
  const int qp  = (lane & 3) << 1;
#pragma unroll
  for (int mf = 0; mf < 2; mf++) {
#pragma unroll
    for (int nf = 0; nf < 4; nf++) {
#pragma unroll
      for (int h8 = 0; h8 < 2; h8++) {
        int rl = wm * 32 + mf * 16 + grp + h8 * 8;
        if (rl < nrows) {
          float h1a = c1[mf][nf][h8 * 2 + 0];
          float h1b = c1[mf][nf][h8 * 2 + 1];
          float h2a = c2[mf][nf][h8 * 2 + 0];
          float h2b = c2[mf][nf][h8 * 2 + 1];
          float ga = (h1a / (1.f + __expf(-h1a))) * h2a;
          float gb = (h1b / (1.f + __expf(-h1b))) * h2b;
          size_t o = (size_t)(row0 + rl) * I_DIM + (n0 + wn * 32 + nf * 8 + qp);
          *(__half2*)&g_gated[o] = __floats2half2_rn(ga, gb);
        }
      }
    }
  }
}

// ------------------- GEMM2: out_sorted = gated * W3 -------------------
__global__ __launch_bounds__(256, 2)
void gemm2_kernel(const float* __restrict__ w3) {
  int tile = blockIdx.y;
  if (tile >= g_ntiles) return;
  const int tid = threadIdx.x;
  const int e = g_tile_e[tile];
  const int row0 = g_tile_row[tile];
  const int nrows = g_tile_nrows[tile];
  const int n0 = blockIdx.x * BN;
  const float* __restrict__ W3 = w3 + (size_t)e * I_DIM * D_DIM;

  __shared__ __half As[BM][BK + 8];
  __shared__ __half Bs[BK][BN + 8];

  float c[2][4][4];
#pragma unroll
  for (int i = 0; i < 2; i++)
#pragma unroll
    for (int j = 0; j < 4; j++)
#pragma unroll
      for (int q = 0; q < 4; q++) c[i][j][q] = 0.f;

  const int lane = tid & 31;
  const int wid = tid >> 5;
  const int wm = wid >> 1;
  const int wn = wid & 1;

  const int arow = tid & 127;
  const int acs  = (tid >> 7) << 4;
  const int brow = tid & 31;
  const int bcs  = (tid >> 5) << 3;

  int asrc = row0 + arow; if (asrc >= TRX) asrc = TRX - 1;
  const __half* agp = &g_gated[(size_t)asrc * I_DIM + acs];

  for (int k0 = 0; k0 < I_DIM; k0 += BK) {
    *(uint4*)&As[arow][acs]     = *(const uint4*)(agp + k0);
    *(uint4*)&As[arow][acs + 8] = *(const uint4*)(agp + k0 + 8);
    {
      size_t g = (size_t)(k0 + brow) * D_DIM + n0 + bcs;
      float4 f0 = *(const float4*)(W3 + g);
      float4 f1 = *(const float4*)(W3 + g + 4);
      __align__(16) __half t[8];
      t[0]=__float2half(f0.x); t[1]=__float2half(f0.y); t[2]=__float2half(f0.z); t[3]=__float2half(f0.w);
      t[4]=__float2half(f1.x); t[5]=__float2half(f1.y); t[6]=__float2half(f1.z); t[7]=__float2half(f1.w);
      *(uint4*)&Bs[brow][bcs] = *(uint4*)t;
    }
    __syncthreads();

#pragma unroll
    for (int kk = 0; kk < BK; kk += 16) {
      uint32_t a[2][4];
#pragma unroll
      for (int mf = 0; mf < 2; mf++) {
        uint32_t ad = smem_u32(&As[wm * 32 + mf * 16 + (lane & 15)][kk + ((lane >> 4) << 3)]);
        asm volatile("ldmatrix.sync.aligned.m8n8.x4.shared.b16 {%0,%1,%2,%3}, [%4];"
          : "=r"(a[mf][0]), "=r"(a[mf][1]), "=r"(a[mf][2]), "=r"(a[mf][3]) : "r"(ad));
      }
#pragma unroll
      for (int nf = 0; nf < 4; nf++) {
        uint32_t b[2];
        uint32_t ad = smem_u32(&Bs[kk + (lane & 15)][wn * 32 + nf * 8]);
        asm volatile("ldmatrix.sync.aligned.m8n8.x2.trans.shared.b16 {%0,%1}, [%2];"
          : "=r"(b[0]), "=r"(b[1]) : "r"(ad));
        mma16816(c[0][nf], a[0], b);
        mma16816(c[1][nf], a[1], b);
      }
    }
    __syncthreads();
  }

  const int grp = lane >> 2;
  const int qp  = (lane & 3) << 1;
#pragma unroll
  for (int mf = 0; mf < 2; mf++) {
#pragma unroll
    for (int nf = 0; nf < 4; nf++) {
#pragma unroll
      for (int h8 = 0; h8 < 2; h8++) {
        int rl = wm * 32 + mf * 16 + grp + h8 * 8;
        if (rl < nrows) {
          size_t o = (size_t)(row0 + rl) * D_DIM + (n0 + wn * 32 + nf * 8 + qp);
          float2 v = make_float2(c[mf][nf][h8 * 2 + 0], c[mf][nf][h8 * 2 + 1]);
          *(float2*)&g_outsorted[o] = v;
        }
      }
    }
  }
}

// ------------------- combine + aux -------------------
__global__ void combine_kernel(float* __restrict__ out) {
  int t = blockIdx.x;
  int p0 = g_dest[t * 2 + 0];
  int p1 = g_dest[t * 2 + 1];
  float w0 = g_topk_w[t * 2 + 0];
  float w1 = g_topk_w[t * 2 + 1];
  const float4* s0 = (const float4*)&g_outsorted[(size_t)p0 * D_DIM];
  const float4* s1 = (const float4*)&g_outsorted[(size_t)p1 * D_DIM];
  float4* o = (float4*)(out + (size_t)t * D_DIM);
  int i = threadIdx.x;  // 256 threads x float4 = 1024 floats
  float4 a = s0[i], b = s1[i];
  float4 r;
  r.x = w0 * a.x + w1 * b.x;
  r.y = w0 * a.y + w1 * b.y;
  r.z = w0 * a.z + w1 * b.z;
  r.w = w0 * a.w + w1 * b.w;
  o[i] = r;
}

__global__ void aux_kernel(float* __restrict__ aux) {
  int t = threadIdx.x;
  if (t < E_EXP) aux[t] = (float)g_counts[t] / (float)TRX;
  if (t == 0) {
    float lbl = 0.f;
    for (int e = 0; e < E_EXP; e++) {
      float f = ((float)g_counts[e] / (float)TRX) * ((float)E_EXP / 2.f);
      float pm = g_probs_sum[e] / (float)T_TOK;
      lbl += f * pm;
    }
    aux[E_EXP]     = 0.01f  * lbl;
    aux[E_EXP + 1] = 0.001f * (g_z2_sum / (float)T_TOK);
  }
}

// ------------------------------- launch -------------------------------
extern "C" void kernel_launch(void* const* d_in, const int* in_sizes, int n_in,
                              void* d_out, int out_size) {
  const float* x  = (const float*)d_in[0];
  const float* rw = (const float*)d_in[1];
  const float* w1 = (const float*)d_in[2];
  const float* w2 = (const float*)d_in[3];
  const float* w3 = (const float*)d_in[4];
  float* out = (float*)d_out;

  zero_kernel<<<1, 32>>>();
  router_kernel<<<T_TOK / 8, 256>>>(x, rw);
  scan_kernel<<<1, 1>>>();
  scatter_kernel<<<TRX / 256, 256>>>();
  gemm1_kernel<<<dim3(I_DIM / BN, GRID_TILES), 256>>>(x, w1, w2);
  gemm2_kernel<<<dim3(D_DIM / BN, GRID_TILES), 256>>>(w3);
  combine_kernel<<<T_TOK, 256>>>(out);
  aux_kernel<<<1, 32>>>(out + (size_t)T_TOK * D_DIM);
}

// round 2
// speedup vs baseline: 2.2785x; 2.2785x over previous
#include <cuda_runtime.h>
#include <cuda_fp16.h>
#include <cstdint>

#define T_TOK 8192
#define D_DIM 1024
#define E_EXP 8
#define I_DIM 3072
#define TRX   16384     // T_TOK * 2 expanded rows
#define BM 128
#define BN 64
#define BK 32
#define MAXT 144
#define GRID_TILES 136

// ------------------- device scratch (static: no allocation) -------------------
__device__ int    g_topk_idx[TRX];
__device__ float  g_topk_w[TRX];
__device__ int    g_counts[E_EXP];
__device__ int    g_cursor[E_EXP];
__device__ float  g_probs_sum[E_EXP];
__device__ float  g_z2_sum;
__device__ int    g_perm_src[TRX];
__device__ int    g_dest[TRX];
__device__ int    g_tile_e[MAXT];
__device__ int    g_tile_row[MAXT];
__device__ int    g_tile_nrows[MAXT];
__device__ int    g_ntiles;
__device__ __half g_gated[(size_t)TRX * I_DIM];       // ~100 MB
__device__ float  g_outsorted[(size_t)TRX * D_DIM];   // ~67 MB
// fp16 mirrors of inputs (converted once per launch)
__device__ __half g_w1h[(size_t)E_EXP * D_DIM * I_DIM]; // ~50 MB
__device__ __half g_w2h[(size_t)E_EXP * D_DIM * I_DIM]; // ~50 MB
__device__ __half g_w3h[(size_t)E_EXP * I_DIM * D_DIM]; // ~50 MB
__device__ __half g_xh[(size_t)T_TOK * D_DIM];          // ~17 MB

__device__ __forceinline__ uint32_t smem_u32(const void* p) {
  return (uint32_t)__cvta_generic_to_shared(p);
}

#define CP_ASYNC16(dst_u32, src_ptr) \
  asm volatile("cp.async.cg.shared.global [%0], [%1], 16;\n" :: "r"(dst_u32), "l"(src_ptr))
#define CP_COMMIT() asm volatile("cp.async.commit_group;\n" ::)
#define CP_WAIT(N)  asm volatile("cp.async.wait_group %0;\n" :: "n"(N))

__device__ __forceinline__ void mma16816(float* c, const uint32_t* a, const uint32_t* b) {
  asm volatile(
    "mma.sync.aligned.m16n8k16.row.col.f32.f16.f16.f32 "
    "{%0,%1,%2,%3}, {%4,%5,%6,%7}, {%8,%9}, {%0,%1,%2,%3};\n"
    : "+f"(c[0]), "+f"(c[1]), "+f"(c[2]), "+f"(c[3])
    : "r"(a[0]), "r"(a[1]), "r"(a[2]), "r"(a[3]), "r"(b[0]), "r"(b[1]));
}

// ------------------------------- conversion -------------------------------
// which: 0->w1h, 1->w2h, 2->w3h, 3->xh
__global__ void cvt_kernel(const float* __restrict__ src, int which, int n) {
  int i = (blockIdx.x * blockDim.x + threadIdx.x) * 8;
  if (i >= n) return;
  __half* dst = (which == 0) ? g_w1h : (which == 1) ? g_w2h : (which == 2) ? g_w3h : g_xh;
  float4 a = *(const float4*)(src + i);
  float4 b = *(const float4*)(src + i + 4);
  __align__(16) __half2 h[4];
  h[0] = __floats2half2_rn(a.x, a.y);
  h[1] = __floats2half2_rn(a.z, a.w);
  h[2] = __floats2half2_rn(b.x, b.y);
  h[3] = __floats2half2_rn(b.z, b.w);
  *(uint4*)(dst + i) = *(uint4*)h;
}

// ------------------------------- small kernels --------------------------------
__global__ void zero_kernel() {
  int t = threadIdx.x;
  if (t < E_EXP) { g_counts[t] = 0; g_cursor[t] = 0; g_probs_sum[t] = 0.f; }
  if (t == 0) { g_z2_sum = 0.f; g_ntiles = 0; }
}

__global__ void router_kernel(const float* __restrict__ x, const float* __restrict__ rw) {
  int warp = threadIdx.x >> 5;
  int lane = threadIdx.x & 31;
  int token = blockIdx.x * 8 + warp;
  const float* xr = x + (size_t)token * D_DIM;
  float acc[E_EXP];
#pragma unroll
  for (int e = 0; e < E_EXP; e++) acc[e] = 0.f;
  for (int i = lane; i < D_DIM; i += 32) {
    float xv = xr[i];
    const float4* w4 = reinterpret_cast<const float4*>(rw + (size_t)i * E_EXP);
    float4 wa = w4[0], wb = w4[1];
    acc[0] += xv * wa.x; acc[1] += xv * wa.y; acc[2] += xv * wa.z; acc[3] += xv * wa.w;
    acc[4] += xv * wb.x; acc[5] += xv * wb.y; acc[6] += xv * wb.z; acc[7] += xv * wb.w;
  }
#pragma unroll
  for (int e = 0; e < E_EXP; e++) {
#pragma unroll
    for (int o = 16; o > 0; o >>= 1) acc[e] += __shfl_xor_sync(0xffffffffu, acc[e], o);
  }
  if (lane == 0) {
    float m = acc[0];
#pragma unroll
    for (int e = 1; e < E_EXP; e++) m = fmaxf(m, acc[e]);
    float p[E_EXP]; float se = 0.f;
#pragma unroll
    for (int e = 0; e < E_EXP; e++) { p[e] = expf(acc[e] - m); se += p[e]; }
    float inv = 1.f / se;
#pragma unroll
    for (int e = 0; e < E_EXP; e++) p[e] *= inv;
    float z = m + logf(se);
    atomicAdd(&g_z2_sum, z * z);
#pragma unroll
    for (int e = 0; e < E_EXP; e++) atomicAdd(&g_probs_sum[e], p[e]);
    int i0 = 0;
#pragma unroll
    for (int e = 1; e < E_EXP; e++) if (acc[e] > acc[i0]) i0 = e;
    int i1 = (i0 == 0) ? 1 : 0;
#pragma unroll
    for (int e = 0; e < E_EXP; e++) if (e != i0 && acc[e] > acc[i1]) i1 = e;
    float s = p[i0] + p[i1];
    g_topk_idx[token * 2 + 0] = i0;
    g_topk_idx[token * 2 + 1] = i1;
    g_topk_w[token * 2 + 0] = p[i0] / s;
    g_topk_w[token * 2 + 1] = p[i1] / s;
    atomicAdd(&g_counts[i0], 1);
    atomicAdd(&g_counts[i1], 1);
  }
}

__global__ void scan_kernel() {
  if (threadIdx.x == 0) {
    int off = 0, nt = 0;
    for (int e = 0; e < E_EXP; e++) {
      g_cursor[e] = off;
      int c = g_counts[e];
      for (int r = 0; r < c; r += BM) {
        g_tile_e[nt] = e;
        g_tile_row[nt] = off + r;
        g_tile_nrows[nt] = (c - r < BM) ? (c - r) : BM;
        nt++;
      }
      off += c;
    }
    g_ntiles = nt;
  }
}

__global__ void scatter_kernel() {
  int i = blockIdx.x * 256 + threadIdx.x;
  if (i < TRX) {
    int e = g_topk_idx[i];
    int pos = atomicAdd(&g_cursor[e], 1);
    g_perm_src[pos] = i >> 1;
    g_dest[i] = pos;
  }
}

// ------------------- GEMM1: gated = silu(Xg*W1) * (Xg*W2) -------------------
// A: fp16 gathered from g_xh, B: fp16 pre-converted weights, cp.async double buffer.
__global__ __launch_bounds__(256, 2)
void gemm1_kernel() {
  int tile = blockIdx.y;
  if (tile >= g_ntiles) return;
  const int tid = threadIdx.x;
  const int e = g_tile_e[tile];
  const int row0 = g_tile_row[tile];
  const int nrows = g_tile_nrows[tile];
  const int n0 = blockIdx.x * BN;
  const __half* __restrict__ W1 = g_w1h + (size_t)e * D_DIM * I_DIM;
  const __half* __restrict__ W2 = g_w2h + (size_t)e * D_DIM * I_DIM;

  __shared__ __half As[2][BM][40];     // 40-half stride = 80B (16B-aligned rows)
  __shared__ __half B1s[2][BK][72];    // 144B stride
  __shared__ __half B2s[2][BK][72];
  __shared__ int rowtok[BM];

  if (tid < BM) {
    int r = row0 + tid;
    rowtok[tid] = g_perm_src[r < TRX ? r : TRX - 1];
  }
  __syncthreads();

  // --- cp.async thread mapping ---
  // A: 512 x 16B chunks (128 rows x 4 chunks) -> 2 per thread
  const int ar0 = tid >> 2;              // chunk tid      : row tid/4
  const int ac0 = (tid & 3) << 3;        //                : col (tid%4)*8 halves
  const int ar1 = (tid + 256) >> 2;
  const int ac1 = ((tid + 256) & 3) << 3;
  // B: 256 x 16B chunks (32 rows x 8 chunks) -> 1 per thread per matrix
  const int br = tid >> 3;
  const int bc = (tid & 7) << 3;

  const __half* a0p = g_xh + (size_t)rowtok[ar0] * D_DIM + ac0;
  const __half* a1p = g_xh + (size_t)rowtok[ar1] * D_DIM + ac1;

  float c1[2][4][4];
  float c2[2][4][4];
#pragma unroll
  for (int i = 0; i < 2; i++)
#pragma unroll
    for (int j = 0; j < 4; j++)
#pragma unroll
      for (int q = 0; q < 4; q++) { c1[i][j][q] = 0.f; c2[i][j][q] = 0.f; }

  const int lane = tid & 31;
  const int wid = tid >> 5;
  const int wm = wid >> 1;
  const int wn = wid & 1;

  // prefetch stage 0
  {
    CP_ASYNC16(smem_u32(&As[0][ar0][ac0]), a0p);
    CP_ASYNC16(smem_u32(&As[0][ar1][ac1]), a1p);
    size_t g = (size_t)br * I_DIM + n0 + bc;
    CP_ASYNC16(smem_u32(&B1s[0][br][bc]), W1 + g);
    CP_ASYNC16(smem_u32(&B2s[0][br][bc]), W2 + g);
    CP_COMMIT();
  }

  const int NK = D_DIM / BK;
#pragma unroll 1
  for (int it = 0; it < NK; it++) {
    int buf = it & 1;
    if (it + 1 < NK) {
      int k0 = (it + 1) * BK;
      CP_ASYNC16(smem_u32(&As[buf ^ 1][ar0][ac0]), a0p + k0);
      CP_ASYNC16(smem_u32(&As[buf ^ 1][ar1][ac1]), a1p + k0);
      size_t g = (size_t)(k0 + br) * I_DIM + n0 + bc;
      CP_ASYNC16(smem_u32(&B1s[buf ^ 1][br][bc]), W1 + g);
      CP_ASYNC16(smem_u32(&B2s[buf ^ 1][br][bc]), W2 + g);
      CP_COMMIT();
      CP_WAIT(1);
    } else {
      CP_WAIT(0);
    }
    __syncthreads();

#pragma unroll
    for (int kk = 0; kk < BK; kk += 16) {
      uint32_t a[2][4];
#pragma unroll
      for (int mf = 0; mf < 2; mf++) {
        uint32_t ad = smem_u32(&As[buf][wm * 32 + mf * 16 + (lane & 15)][kk + ((lane >> 4) << 3)]);
        asm volatile("ldmatrix.sync.aligned.m8n8.x4.shared.b16 {%0,%1,%2,%3}, [%4];"
          : "=r"(a[mf][0]), "=r"(a[mf][1]), "=r"(a[mf][2]), "=r"(a[mf][3]) : "r"(ad));
      }
#pragma unroll
      for (int nf = 0; nf < 4; nf++) {
        uint32_t b[2];
        uint32_t ad1 = smem_u32(&B1s[buf][kk + (lane & 15)][wn * 32 + nf * 8]);
        asm volatile("ldmatrix.sync.aligned.m8n8.x2.trans.shared.b16 {%0,%1}, [%2];"
          : "=r"(b[0]), "=r"(b[1]) : "r"(ad1));
        mma16816(c1[0][nf], a[0], b);
        mma16816(c1[1][nf], a[1], b);
        uint32_t ad2 = smem_u32(&B2s[buf][kk + (lane & 15)][wn * 32 + nf * 8]);
        asm volatile("ldmatrix.sync.aligned.m8n8.x2.trans.shared.b16 {%0,%1}, [%2];"
          : "=r"(b[0]), "=r"(b[1]) : "r"(ad2));
        mma16816(c2[0][nf], a[0], b);
        mma16816(c2[1][nf], a[1], b);
      }
    }
    __syncthreads();
  }

  const int grp = lane >> 2;
  const int qp  = (lane & 3) << 1;
#pragma unroll
  for (int mf = 0; mf < 2; mf++) {
#pragma unroll
    for (int nf = 0; nf < 4; nf++) {
#pragma unroll
      for (int h8 = 0; h8 < 2; h8++) {
        int rl = wm * 32 + mf * 16 + grp + h8 * 8;
        if (rl < nrows) {
          float h1a = c1[mf][nf][h8 * 2 + 0];
          float h1b = c1[mf][nf][h8 * 2 + 1];
          float h2a = c2[mf][nf][h8 * 2 + 0];
          float h2b = c2[mf][nf][h8 * 2 + 1];
          float ga = (h1a / (1.f + __expf(-h1a))) * h2a;
          float gb = (h1b / (1.f + __expf(-h1b))) * h2b;
          size_t o = (size_t)(row0 + rl) * I_DIM + (n0 + wn * 32 + nf * 8 + qp);
          *(__half2*)&g_gated[o] = __floats2half2_rn(ga, gb);
        }
      }
    }
  }
}

// ------------------- GEMM2: out_sorted = gated * W3 -------------------
__global__ __launch_bounds__(256, 2)
void gemm2_kernel() {
  int tile = blockIdx.y;
  if (tile >= g_ntiles) return;
  const int tid = threadIdx.x;
  const int e = g_tile_e[tile];
  const int row0 = g_tile_row[tile];
  const int nrows = g_tile_nrows[tile];
  const int n0 = blockIdx.x * BN;
  const __half* __restrict__ W3 = g_w3h + (size_t)e * I_DIM * D_DIM;

  __shared__ __half As[2][BM][40];
  __shared__ __half Bs[2][BK][72];

  float c[2][4][4];
#pragma unroll
  for (int i = 0; i < 2; i++)
#pragma unroll
    for (int j = 0; j < 4; j++)
#pragma unroll
      for (int q = 0; q < 4; q++) c[i][j][q] = 0.f;

  const int lane = tid & 31;
  const int wid = tid >> 5;
  const int wm = wid >> 1;
  const int wn = wid & 1;

  const int ar0 = tid >> 2;
  const int ac0 = (tid & 3) << 3;
  const int ar1 = (tid + 256) >> 2;
  const int ac1 = ((tid + 256) & 3) << 3;
  const int br = tid >> 3;
  const int bc = (tid & 7) << 3;

  int s0 = row0 + ar0; if (s0 >= TRX) s0 = TRX - 1;
  int s1 = row0 + ar1; if (s1 >= TRX) s1 = TRX - 1;
  const __half* a0p = g_gated + (size_t)s0 * I_DIM + ac0;
  const __half* a1p = g_gated + (size_t)s1 * I_DIM + ac1;

  {
    CP_ASYNC16(smem_u32(&As[0][ar0][ac0]), a0p);
    CP_ASYNC16(smem_u32(&As[0][ar1][ac1]), a1p);
    size_t g = (size_t)br * D_DIM + n0 + bc;
    CP_ASYNC16(smem_u32(&Bs[0][br][bc]), W3 + g);
    CP_COMMIT();
  }

  const int NK = I_DIM / BK;
#pragma unroll 1
  for (int it = 0; it < NK; it++) {
    int buf = it & 1;
    if (it + 1 < NK) {
      int k0 = (it + 1) * BK;
      CP_ASYNC16(smem_u32(&As[buf ^ 1][ar0][ac0]), a0p + k0);
      CP_ASYNC16(smem_u32(&As[buf ^ 1][ar1][ac1]), a1p + k0);
      size_t g = (size_t)(k0 + br) * D_DIM + n0 + bc;
      CP_ASYNC16(smem_u32(&Bs[buf ^ 1][br][bc]), W3 + g);
      CP_COMMIT();
      CP_WAIT(1);
    } else {
      CP_WAIT(0);
    }
    __syncthreads();

#pragma unroll
    for (int kk = 0; kk < BK; kk += 16) {
      uint32_t a[2][4];
#pragma unroll
      for (int mf = 0; mf < 2; mf++) {
        uint32_t ad = smem_u32(&As[buf][wm * 32 + mf * 16 + (lane & 15)][kk + ((lane >> 4) << 3)]);
        asm volatile("ldmatrix.sync.aligned.m8n8.x4.shared.b16 {%0,%1,%2,%3}, [%4];"
          : "=r"(a[mf][0]), "=r"(a[mf][1]), "=r"(a[mf][2]), "=r"(a[mf][3]) : "r"(ad));
      }
#pragma unroll
      for (int nf = 0; nf < 4; nf++) {
        uint32_t b[2];
        uint32_t ad = smem_u32(&Bs[buf][kk + (lane & 15)][wn * 32 + nf * 8]);
        asm volatile("ldmatrix.sync.aligned.m8n8.x2.trans.shared.b16 {%0,%1}, [%2];"
          : "=r"(b[0]), "=r"(b[1]) : "r"(ad));
        mma16816(c[0][nf], a[0], b);
        mma16816(c[1][nf], a[1], b);
      }
    }
    __syncthreads();
  }

  const int grp = lane >> 2;
  const int qp  = (lane & 3) << 1;
#pragma unroll
  for (int mf = 0; mf < 2; mf++) {
#pragma unroll
    for (int nf = 0; nf < 4; nf++) {
#pragma unroll
      for (int h8 = 0; h8 < 2; h8++) {
        int rl = wm * 32 + mf * 16 + grp + h8 * 8;
        if (rl < nrows) {
          size_t o = (size_t)(row0 + rl) * D_DIM + (n0 + wn * 32 + nf * 8 + qp);
          float2 v = make_float2(c[mf][nf][h8 * 2 + 0], c[mf][nf][h8 * 2 + 1]);
          *(float2*)&g_outsorted[o] = v;
        }
      }
    }
  }
}

// ------------------- combine + aux -------------------
__global__ void combine_kernel(float* __restrict__ out) {
  int t = blockIdx.x;
  int p0 = g_dest[t * 2 + 0];
  int p1 = g_dest[t * 2 + 1];
  float w0 = g_topk_w[t * 2 + 0];
  float w1 = g_topk_w[t * 2 + 1];
  const float4* s0 = (const float4*)&g_outsorted[(size_t)p0 * D_DIM];
  const float4* s1 = (const float4*)&g_outsorted[(size_t)p1 * D_DIM];
  float4* o = (float4*)(out + (size_t)t * D_DIM);
  int i = threadIdx.x;
  float4 a = s0[i], b = s1[i];
  float4 r;
  r.x = w0 * a.x + w1 * b.x;
  r.y = w0 * a.y + w1 * b.y;
  r.z = w0 * a.z + w1 * b.z;
  r.w = w0 * a.w + w1 * b.w;
  o[i] = r;
}

__global__ void aux_kernel(float* __restrict__ aux) {
  int t = threadIdx.x;
  if (t < E_EXP) aux[t] = (float)g_counts[t] / (float)TRX;
  if (t == 0) {
    float lbl = 0.f;
    for (int e = 0; e < E_EXP; e++) {
      float f = ((float)g_counts[e] / (float)TRX) * ((float)E_EXP / 2.f);
      float pm = g_probs_sum[e] / (float)T_TOK;
      lbl += f * pm;
    }
    aux[E_EXP]     = 0.01f  * lbl;
    aux[E_EXP + 1] = 0.001f * (g_z2_sum / (float)T_TOK);
  }
}

// ------------------------------- launch -------------------------------
extern "C" void kernel_launch(void* const* d_in, const int* in_sizes, int n_in,
                              void* d_out, int out_size) {
  const float* x  = (const float*)d_in[0];
  const float* rw = (const float*)d_in[1];
  const float* w1 = (const float*)d_in[2];
  const float* w2 = (const float*)d_in[3];
  const float* w3 = (const float*)d_in[4];
  float* out = (float*)d_out;

  const int WN = E_EXP * D_DIM * I_DIM;   // 25165824
  const int XN = T_TOK * D_DIM;           // 8388608

  cvt_kernel<<<WN / 8 / 256, 256>>>(w1, 0, WN);
  cvt_kernel<<<WN / 8 / 256, 256>>>(w2, 1, WN);
  cvt_kernel<<<WN / 8 / 256, 256>>>(w3, 2, WN);
  cvt_kernel<<<XN / 8 / 256, 256>>>(x, 3, XN);

  zero_kernel<<<1, 32>>>();
  router_kernel<<<T_TOK / 8, 256>>>(x, rw);
  scan_kernel<<<1, 1>>>();
  scatter_kernel<<<TRX / 256, 256>>>();
  gemm1_kernel<<<dim3(I_DIM / BN, GRID_TILES), 256>>>();
  gemm2_kernel<<<dim3(D_DIM / BN, GRID_TILES), 256>>>();
  combine_kernel<<<T_TOK, 256>>>(out);
  aux_kernel<<<1, 32>>>(out + (size_t)T_TOK * D_DIM);
}